// round 5
// baseline (speedup 1.0000x reference)
#include <cuda_runtime.h>
#include <cuda_bf16.h>

// QuantumSubgenerator: 12-qubit RY / CNOT-ring / RY circuit + <Z_q> readout,
// reduced exactly (Heisenberg picture) to closed-form trig products:
//
//   alpha_q = latent[b][q] + w0[q];  c_q=cos(alpha_q), s_q=sin(alpha_q)
//   out[b][0]  = cos(th_0) * prod_{1..11} c_r  - sin(th_0)*s_0*s_1
//   out[b][q]  = cos(th_q) * prod_{0..q}  c_r  - sin(th_q)*s_q*s_{q+1}  (1<=q<=10)
//   out[b][11] = cos(th_11)* prod_{0..11} c_r  - sin(th_11)*s_0*s_1*s_11
//
// Round 5: best-known config (128 CTAs x 128 threads, 8 elems/CTA, one wave
// over 128 SMs — R3) + branch-free front end from R4 (clamped indices so the
// LDGs issue unconditionally at instruction 0; only the STG is guarded).

#define NQ 12
#define FULL 0xFFFFFFFFu

__global__ void __launch_bounds__(128)
QuantumSubgenerator_25314537242888_kernel(const float* __restrict__ latent,
                                          const float* __restrict__ weights,
                                          float* __restrict__ out, int B) {
    int seg = threadIdx.x >> 4;                  // 8 segments per block
    int q   = threadIdx.x & 15;                  // lane within segment
    int b   = blockIdx.x * 8 + seg;              // batch element
    int ql  = q < NQ - 1 ? q : NQ - 1;           // clamped (keeps loads in-bounds)
    int bl  = b < B ? b : B - 1;

    // Unconditional loads — issue immediately, no guard branch in front.
    float lat = latent[(size_t)bl * NQ + ql];
    float w0  = __ldg(&weights[ql]);
    float w1  = __ldg(&weights[NQ + ql]);

    float c, s, cw, sw;
    __sincosf(lat + w0, &s, &c);                 // MUFU fast path, pipelined
    __sincosf(w1, &sw, &cw);

    // Segmented (width=16) inclusive prefix product of c over lanes 1..q:
    // cp_q = prod_{1..q} c_r   (lane 0 contributes 1).
    float cp = (q == 0) ? 1.0f : c;
    #pragma unroll
    for (int d = 1; d < 16; d <<= 1) {
        float v = __shfl_up_sync(FULL, cp, d, 16);
        if (q >= d) cp *= v;
    }

    // Segment broadcasts (independent -> pipelined).
    float c0   = __shfl_sync(FULL, c,  0, 16);
    float s0   = __shfl_sync(FULL, s,  0, 16);
    float s1   = __shfl_sync(FULL, s,  1, 16);
    float ptot = __shfl_sync(FULL, cp, NQ - 1, 16);   // prod_{1..11} c_r
    float snx  = __shfl_down_sync(FULL, s, 1, 16);    // s_{q+1}

    float o;
    if (q == 0) {
        o = cw * ptot - sw * (s0 * s1);
    } else if (q >= NQ - 1) {
        o = cw * (c0 * ptot) - sw * (s0 * s1 * s);
    } else {
        o = cw * (c0 * cp) - sw * (s * snx);
    }

    if (q < NQ && b < B)
        out[(size_t)b * NQ + q] = o;
}

extern "C" void kernel_launch(void* const* d_in, const int* in_sizes, int n_in,
                              void* d_out, int out_size) {
    const float* latent  = (const float*)d_in[0];
    const float* weights = (const float*)d_in[1];
    int lat_sz = in_sizes[0];
    // Robust to input-order surprises: weights tensor has exactly 2*NQ elems.
    if (n_in >= 2 && in_sizes[0] == 2 * NQ) {
        latent  = (const float*)d_in[1];
        weights = (const float*)d_in[0];
        lat_sz  = in_sizes[1];
    }
    int B = lat_sz / NQ;                 // 1024
    int blocks = (B + 7) / 8;            // 8 elements per 128-thread block
    QuantumSubgenerator_25314537242888_kernel<<<blocks, 128>>>(
        latent, weights, (float*)d_out, B);
}

// round 6
// speedup vs baseline: 1.5035x; 1.5035x over previous
#include <cuda_runtime.h>
#include <cuda_bf16.h>

// QuantumSubgenerator: 12-qubit RY / CNOT-ring / RY circuit + <Z_q> readout,
// reduced exactly (Heisenberg picture) to closed-form trig products:
//
//   alpha_q = latent[b][q] + w0[q];  c_q=cos(alpha_q), s_q=sin(alpha_q)
//   out[b][0]  = cos(th_0) * prod_{1..11} c_r  - sin(th_0)*s_0*s_1
//   out[b][q]  = cos(th_q) * prod_{0..q}  c_r  - sin(th_q)*s_q*s_{q+1}  (1<=q<=10)
//   out[b][11] = cos(th_11)* prod_{0..11} c_r  - sin(th_11)*s_0*s_1*s_11
//
// Final (= Round-3 winner): lane-parallel, 16 lanes per batch element
// (lanes 0..11 active), 2 elements per warp, 8 per 128-thread block,
// 128 blocks = 1 warp per SMSP across 128 SMs (fully parallel warps).
// Guarded loads (12 active lanes only) measured faster than clamped
// unconditional loads (R5) and than 256-thread blocks (R4). Kernel is at
// the launch-overhead floor: per-warp critical path ~0.3us, total ~4.1us.

#define NQ 12
#define FULL 0xFFFFFFFFu

__global__ void __launch_bounds__(128)
QuantumSubgenerator_25314537242888_kernel(const float* __restrict__ latent,
                                          const float* __restrict__ weights,
                                          float* __restrict__ out, int B) {
    int seg  = threadIdx.x >> 4;                 // which 16-lane segment in block
    int q    = threadIdx.x & 15;                 // lane within segment (qubit id)
    int b    = blockIdx.x * 8 + seg;             // batch element
    bool act = (q < NQ) && (b < B);

    // Per-lane trig: alpha_q = latent + w0_q ; theta_q = w1_q
    float c = 1.0f, s = 0.0f, cw = 1.0f, sw = 0.0f;
    if (act) {
        float a = latent[(size_t)b * NQ + q] + __ldg(&weights[q]);
        __sincosf(a, &s, &c);
        __sincosf(__ldg(&weights[NQ + q]), &sw, &cw);
    }

    // Inclusive prefix product over lanes 1..q of c (lane0 contributes 1):
    // cp_q = prod_{1..q} c_r.  Segmented width-16 scan, 4 steps.
    float cp = (q == 0) ? 1.0f : c;
    #pragma unroll
    for (int d = 1; d < 16; d <<= 1) {
        float v = __shfl_up_sync(FULL, cp, d, 16);
        if (q >= d) cp *= v;
    }

    // Broadcasts within the 16-lane segment (independent -> pipelined).
    float c0   = __shfl_sync(FULL, c,  0, 16);
    float s0   = __shfl_sync(FULL, s,  0, 16);
    float s1   = __shfl_sync(FULL, s,  1, 16);
    float ptot = __shfl_sync(FULL, cp, NQ - 1, 16);   // prod_{1..11} c_r
    float snx  = __shfl_down_sync(FULL, s, 1, 16);    // s_{q+1}

    if (act) {
        float o;
        if (q == 0) {
            o = cw * ptot - sw * (s0 * s1);
        } else if (q == NQ - 1) {
            o = cw * (c0 * ptot) - sw * (s0 * s1 * s);
        } else {
            o = cw * (c0 * cp) - sw * (s * snx);
        }
        out[(size_t)b * NQ + q] = o;
    }
}

extern "C" void kernel_launch(void* const* d_in, const int* in_sizes, int n_in,
                              void* d_out, int out_size) {
    const float* latent  = (const float*)d_in[0];
    const float* weights = (const float*)d_in[1];
    int lat_sz = in_sizes[0];
    // Robust to input-order surprises: weights tensor has exactly 2*NQ elems.
    if (n_in >= 2 && in_sizes[0] == 2 * NQ) {
        latent  = (const float*)d_in[1];
        weights = (const float*)d_in[0];
        lat_sz  = in_sizes[1];
    }
    int B = lat_sz / NQ;                 // 1024
    int blocks = (B + 7) / 8;            // 8 elements per 128-thread block
    QuantumSubgenerator_25314537242888_kernel<<<blocks, 128>>>(
        latent, weights, (float*)d_out, B);
}

// round 7
// speedup vs baseline: 1.5141x; 1.0070x over previous
#include <cuda_runtime.h>
#include <cuda_bf16.h>

// QuantumSubgenerator: 12-qubit RY / CNOT-ring / RY circuit + <Z_q> readout,
// reduced exactly (Heisenberg picture) to closed-form trig products:
//
//   alpha_q = latent[b][q] + w0[q];  c_q=cos(alpha_q), s_q=sin(alpha_q)
//   out[b][0]  = cos(th_0) * prod_{1..11} c_r  - sin(th_0)*s_0*s_1
//   out[b][q]  = cos(th_q) * prod_{0..q}  c_r  - sin(th_q)*s_q*s_{q+1}  (1<=q<=10)
//   out[b][11] = cos(th_11)* prod_{0..11} c_r  - sin(th_11)*s_0*s_1*s_11
//
// Terminal kernel (R3 winner + micro-cleanup): lane-parallel, 16 lanes per
// batch element (lanes 0..11 active), 2 elements per warp, 8 per 128-thread
// block, 128 blocks = 1 warp per SMSP across 128 SMs. Measured at the
// grid-launch floor (~4.1us ncu): critical path ~450 cycles (~0.25us),
// every pipe <0.5% of peak. Config alternatives (256-thread blocks, clamped
// unconditional loads, thread-per-element) all benched slower (R2/R4/R5).

#define NQ 12
#define FULL 0xFFFFFFFFu

__global__ void __launch_bounds__(128)
QuantumSubgenerator_25314537242888_kernel(const float* __restrict__ latent,
                                          const float* __restrict__ weights,
                                          float* __restrict__ out, int B) {
    int seg  = threadIdx.x >> 4;                 // 16-lane segment in block
    int q    = threadIdx.x & 15;                 // lane within segment (qubit id)
    int b    = blockIdx.x * 8 + seg;             // batch element
    int idx  = b * NQ + q;                       // 32-bit index math
    bool act = (q < NQ) && (b < B);

    // Per-lane trig: alpha_q = latent + w0_q ; theta_q = w1_q.
    // Loads grouped so ptxas front-batches the three LDGs (MLP).
    float c = 1.0f, s = 0.0f, cw = 1.0f, sw = 0.0f;
    if (act) {
        float w0  = __ldg(&weights[q]);
        float w1  = __ldg(&weights[NQ + q]);
        float lat = latent[idx];
        __sincosf(lat + w0, &s, &c);             // MUFU fast path, pipelined
        __sincosf(w1, &sw, &cw);
    }

    // Inclusive prefix product over lanes 1..q of c (lane0 contributes 1):
    // cp_q = prod_{1..q} c_r.  Segmented width-16 scan, minimal depth 4.
    float cp = (q == 0) ? 1.0f : c;
    #pragma unroll
    for (int d = 1; d < 16; d <<= 1) {
        float v = __shfl_up_sync(FULL, cp, d, 16);
        if (q >= d) cp *= v;
    }

    // Broadcasts within the 16-lane segment (independent -> pipelined).
    float c0   = __shfl_sync(FULL, c,  0, 16);
    float s0   = __shfl_sync(FULL, s,  0, 16);
    float s1   = __shfl_sync(FULL, s,  1, 16);
    float ptot = __shfl_sync(FULL, cp, NQ - 1, 16);   // prod_{1..11} c_r
    float snx  = __shfl_down_sync(FULL, s, 1, 16);    // s_{q+1}

    if (act) {
        float o;
        if (q == 0) {
            o = cw * ptot - sw * (s0 * s1);
        } else if (q == NQ - 1) {
            o = cw * (c0 * ptot) - sw * (s0 * s1 * s);
        } else {
            o = cw * (c0 * cp) - sw * (s * snx);
        }
        out[idx] = o;
    }
}

extern "C" void kernel_launch(void* const* d_in, const int* in_sizes, int n_in,
                              void* d_out, int out_size) {
    const float* latent  = (const float*)d_in[0];
    const float* weights = (const float*)d_in[1];
    int lat_sz = in_sizes[0];
    // Robust to input-order surprises: weights tensor has exactly 2*NQ elems.
    if (n_in >= 2 && in_sizes[0] == 2 * NQ) {
        latent  = (const float*)d_in[1];
        weights = (const float*)d_in[0];
        lat_sz  = in_sizes[1];
    }
    int B = lat_sz / NQ;                 // 1024
    int blocks = (B + 7) / 8;            // 8 elements per 128-thread block
    QuantumSubgenerator_25314537242888_kernel<<<blocks, 128>>>(
        latent, weights, (float*)d_out, B);
}